// round 16
// baseline (speedup 1.0000x reference)
#include <cuda_runtime.h>
#include <cuda_bf16.h>
#include <cstdint>

#define B_   64
#define T_   2048
#define DIN  128
#define H_   512
#define DOUT 128

#define KC   64      // K elems per chunk (128B bf16 rows)
#define TPB  256

#if defined(__CUDA_ARCH__) && (defined(__CUDA_ARCH_FEAT_SM103_ALL) || defined(__CUDA_ARCH_FEAT_SM100_ALL))
#define USE_TC 1
#else
#define USE_TC 0
#endif

// idesc kind::f16: dtype=F32(1<<4) atype=BF16(1<<7) btype=BF16(1<<10) N=128(16<<17) M=128(8<<24)
#define IDESC_128x128 0x8200490u

// SMEM: [0:4) tmem ptr; mbars at 8 (2x8B); W buf 32KB at 1024; X bufs 2x32KB
#define SM_MB0   8
#define SM_MB1   16
#define SM_W     1024
#define SM_X0    (1024 + 32768)
#define XBUF_SZ  32768
#define SM_TOTAL (1024 + 32768 + 2*32768)   // 99328 -> occ 2; TMEM 2x256=512 OK

// ---------------- scratch: planar bf16 hi/lo ----------------
__device__ __nv_bfloat16 g_xhi[(size_t)B_ * T_ * DIN];
__device__ __nv_bfloat16 g_xlo[(size_t)B_ * T_ * DIN];
__device__ __nv_bfloat16 g_h1hi[(size_t)B_ * T_ * H_];
__device__ __nv_bfloat16 g_h1lo[(size_t)B_ * T_ * H_];
__device__ __nv_bfloat16 g_h2hi[(size_t)B_ * T_ * H_];
__device__ __nv_bfloat16 g_h2lo[(size_t)B_ * T_ * H_];
__device__ __nv_bfloat16 g_W0hi[H_ * DIN];
__device__ __nv_bfloat16 g_W0lo[H_ * DIN];
__device__ __nv_bfloat16 g_W1hi[H_ * H_];
__device__ __nv_bfloat16 g_W1lo[H_ * H_];
__device__ __nv_bfloat16 g_fWhi[DOUT * H_];
__device__ __nv_bfloat16 g_fWlo[DOUT * H_];

#if USE_TC
// ---------------- PTX helpers ----------------
__device__ __forceinline__ uint32_t smem_to_u32(const void* p) {
    uint32_t a;
    asm("{ .reg .u64 t; cvta.to.shared.u64 t, %1; cvt.u32.u64 %0, t; }" : "=r"(a) : "l"(p));
    return a;
}
__device__ __forceinline__ uint32_t elect_one_pred() {
    uint32_t p;
    asm volatile("{\n\t.reg .pred p;\n\telect.sync _|p, 0xFFFFFFFF;\n\tselp.b32 %0, 1, 0, p;\n\t}" : "=r"(p));
    return p;
}
#define MBAR_INIT(a, c) asm volatile("mbarrier.init.shared.b64 [%0], %1;" :: "r"(a), "r"(c) : "memory")
#define MBAR_INVAL(a)   asm volatile("mbarrier.inval.shared.b64 [%0];" :: "r"(a) : "memory")
#define MBAR_WAIT(a, ph) do {                                                       \
    uint32_t _m = (a), _p = (ph), _d;                                               \
    asm volatile("{\n\t.reg .pred p;\n\t"                                           \
        "mbarrier.try_wait.parity.acquire.cta.shared::cta.b64 p, [%1], %2;\n\t"     \
        "selp.b32 %0, 1, 0, p;\n\t}" : "=r"(_d) : "r"(_m), "r"(_p) : "memory");     \
    if (!_d) {                                                                      \
        asm volatile("{\n\t.reg .pred P1;\n\tWL_%=:\n\t"                            \
            "mbarrier.try_wait.parity.acquire.cta.shared::cta.b64 P1, [%0], %1, 0x989680;\n\t" \
            "@P1 bra.uni WD_%=;\n\tbra.uni WL_%=;\n\tWD_%=:\n\t}"                   \
            :: "r"(_m), "r"(_p) : "memory");                                        \
    }                                                                               \
} while (0)
#define TC_ALLOC(sa, n)   asm volatile("tcgen05.alloc.cta_group::1.sync.aligned.shared::cta.b32 [%0], %1;" :: "r"(sa), "r"(n) : "memory")
#define TC_DEALLOC(t, n)  asm volatile("tcgen05.dealloc.cta_group::1.sync.aligned.b32 %0, %1;" :: "r"(t), "r"(n))
#define TC_RELINQ()       asm volatile("tcgen05.relinquish_alloc_permit.cta_group::1.sync.aligned;")
#define TC_COMMIT(mb)     asm volatile("tcgen05.commit.cta_group::1.mbarrier::arrive::one.shared::cluster.b64 [%0];" :: "r"(mb) : "memory")
#define TC_WAIT_LD()      asm volatile("tcgen05.wait::ld.sync.aligned;" ::: "memory")
#define TC_FENCE_BEFORE() asm volatile("tcgen05.fence::before_thread_sync;" ::: "memory")
#define TC_FENCE_AFTER()  asm volatile("tcgen05.fence::after_thread_sync;" ::: "memory")
#define FENCE_ASYNC()     asm volatile("fence.proxy.async.shared::cta;" ::: "memory")
#define CP_ASYNC16(d, s)  asm volatile("cp.async.cg.shared.global [%0], [%1], 16;" :: "r"(d), "l"(s) : "memory")
#define CP_COMMIT()       asm volatile("cp.async.commit_group;" ::: "memory")
#define CP_WAIT0()        asm volatile("cp.async.wait_group 0;" ::: "memory")

__device__ __forceinline__ void mma_f16_ss(uint32_t d, uint64_t ad, uint64_t bd, uint32_t en) {
    asm volatile(
        "{\n\t.reg .pred p;\n\tsetp.ne.u32 p, %4, 0;\n\t"
        "tcgen05.mma.cta_group::1.kind::f16 [%0], %1, %2, %3, {%5, %5, %5, %5}, p;\n\t}"
        :: "r"(d), "l"(ad), "l"(bd), "r"(IDESC_128x128), "r"(en), "r"(0u) : "memory");
}
__device__ __forceinline__ uint64_t mk_desc(uint32_t addr) {
    return ((uint64_t)2 << 61) | ((uint64_t)1 << 46) | ((uint64_t)64 << 32)
         | ((uint64_t)1 << 16) | ((uint64_t)(addr >> 4) & 0x3FFF);
}
#define LDTM_X32(r, a)                                                              \
    asm volatile("tcgen05.ld.sync.aligned.32x32b.x32.b32 "                          \
        "{%0,%1,%2,%3,%4,%5,%6,%7,%8,%9,%10,%11,%12,%13,%14,%15,"                   \
        "%16,%17,%18,%19,%20,%21,%22,%23,%24,%25,%26,%27,%28,%29,%30,%31}, [%32];"  \
        : "=r"((r)[0]),"=r"((r)[1]),"=r"((r)[2]),"=r"((r)[3]),                       \
          "=r"((r)[4]),"=r"((r)[5]),"=r"((r)[6]),"=r"((r)[7]),                       \
          "=r"((r)[8]),"=r"((r)[9]),"=r"((r)[10]),"=r"((r)[11]),                     \
          "=r"((r)[12]),"=r"((r)[13]),"=r"((r)[14]),"=r"((r)[15]),                   \
          "=r"((r)[16]),"=r"((r)[17]),"=r"((r)[18]),"=r"((r)[19]),                   \
          "=r"((r)[20]),"=r"((r)[21]),"=r"((r)[22]),"=r"((r)[23]),                   \
          "=r"((r)[24]),"=r"((r)[25]),"=r"((r)[26]),"=r"((r)[27]),                   \
          "=r"((r)[28]),"=r"((r)[29]),"=r"((r)[30]),"=r"((r)[31]) : "r"(a))

// load one 128-row x 64-bf16 hi/lo pair: 256 threads, plane = tid>>7, row = tid&127.
__device__ __forceinline__ void load_pair(uint32_t dstbase,
        const __nv_bfloat16* __restrict__ hi, const __nv_bfloat16* __restrict__ lo,
        size_t row0, int K, int kc_e, int tid) {
    const int row = tid & 127;
    const char* src = (const char*)((tid < 128 ? hi : lo) + (row0 + row) * (size_t)K + kc_e);
    const uint32_t dst = dstbase + (uint32_t)(tid >> 7) * 16384;
    #pragma unroll
    for (int p = 0; p < 8; p++) {
        uint32_t off = row * 128 + p * 16;
        uint32_t sw = off ^ ((off >> 3) & 0x70);
        CP_ASYNC16(dst + sw, src + p * 16);
    }
}

// 12 MMA dispatches: (Wh,Xh)+(Wh,Xl)+(Wl,Xh) x 4 K16-steps, N=128.
__device__ __forceinline__ void issue12(uint32_t smb, uint32_t xb, uint32_t dacc, int first) {
    const uint64_t dWH = mk_desc(smb + SM_W), dWL = mk_desc(smb + SM_W + 16384);
    const uint64_t dXH = mk_desc(xb), dXL = mk_desc(xb + 16384);
    #pragma unroll
    for (int k = 0; k < 4; k++) {
        const uint64_t o = (uint64_t)(k * 2);
        mma_f16_ss(dacc, dWH + o, dXH + o, (first && k == 0) ? 0u : 1u);
        mma_f16_ss(dacc, dWH + o, dXL + o, 1u);
        mma_f16_ss(dacc, dWL + o, dXH + o, 1u);
    }
}
#endif  // USE_TC

// ---------------- merged fp32 -> planar bf16 hi/lo split ----------------
__global__ void split_all(const float* __restrict__ x,  const float* __restrict__ W0,
                          const float* __restrict__ W1, const float* __restrict__ fcW,
                          __nv_bfloat16* __restrict__ xhi,  __nv_bfloat16* __restrict__ xlo,
                          __nv_bfloat16* __restrict__ w0hi, __nv_bfloat16* __restrict__ w0lo,
                          __nv_bfloat16* __restrict__ w1hi, __nv_bfloat16* __restrict__ w1lo,
                          __nv_bfloat16* __restrict__ fwhi, __nv_bfloat16* __restrict__ fwlo) {
    const int NX = B_ * T_ * DIN, NW0 = H_ * DIN, NW1 = H_ * H_, NF = DOUT * H_;
    const int total = NX + NW0 + NW1 + NF;
    for (int i = blockIdx.x * blockDim.x + threadIdx.x; i < total; i += gridDim.x * blockDim.x) {
        const float* s; __nv_bfloat16 *ph, *pl; int j;
        if (i < NX)                  { s = x;   ph = xhi;  pl = xlo;  j = i; }
        else if (i < NX + NW0)       { s = W0;  ph = w0hi; pl = w0lo; j = i - NX; }
        else if (i < NX + NW0 + NW1) { s = W1;  ph = w1hi; pl = w1lo; j = i - NX - NW0; }
        else                         { s = fcW; ph = fwhi; pl = fwlo; j = i - NX - NW0 - NW1; }
        float v = s[j];
        __nv_bfloat16 h = __float2bfloat16(v);
        ph[j] = h;
        pl[j] = __float2bfloat16(v - __bfloat162float(h));
    }
}

// ================ unified GEMM kernel: lagged-commit pipeline, TG=2 ================
// EPI_SCAN=1 (layers): grid (H_/128, B_), h0=bx*128, toff=0, NTG=8; scan epilogue.
// EPI_SCAN=0 (fc):     grid (2, B_),      h0=0,      toff=bx*T_/2, NTG=4; bias epilogue.
// occ 2 (99KB smem, TMEM 256 cols/CTA). No MMA drain between steps except W reload.
template <int K, int EPI_SCAN>
__global__ void __launch_bounds__(TPB)
gemm_tc(const __nv_bfloat16* __restrict__ Xhi, const __nv_bfloat16* __restrict__ Xlo,
        const __nv_bfloat16* __restrict__ Whi, const __nv_bfloat16* __restrict__ Wlo,
        const float* __restrict__ bl, const float* __restrict__ u, const float* __restrict__ bb,
        __nv_bfloat16* __restrict__ Hhi, __nv_bfloat16* __restrict__ Hlo,
        float* __restrict__ fout) {
    extern __shared__ char smem[];
    const int tid = threadIdx.x;
    const int batch = blockIdx.y;
    const int h0   = EPI_SCAN ? blockIdx.x * 128 : 0;
    const int toff = EPI_SCAN ? 0 : blockIdx.x * (T_ / 2);
#if USE_TC
    constexpr int C = K / KC;
    constexpr int STEPS = C * 2;                 // TG=2 tiles per group
    constexpr int NTG = EPI_SCAN ? T_ / 256 : T_ / 512;
    const uint32_t smb = smem_to_u32(smem);
    const int wid = tid >> 5;

    if (tid == 0) { MBAR_INIT(smb + SM_MB0, 1); MBAR_INIT(smb + SM_MB1, 1); }
    if (wid == 0) { TC_ALLOC(smb, 256); TC_RELINQ(); }
    __syncthreads();
    uint32_t tmem;
    asm volatile("ld.shared.b32 %0, [%1];" : "=r"(tmem) : "r"(smb));

    float carry = 0.0f, uu = 0.0f, bi = 0.0f;
    if (tid < 128) {
        bi = bl[h0 + tid] + (EPI_SCAN ? bb[h0 + tid] : 0.0f);
        if (EPI_SCAN) uu = u[h0 + tid];
    }

    int c0 = 0, c1 = 0;   // commits issued to mbar0 / mbar1

    // preload tg0 step0: W[kc0] + X[tile0] -> xbuf0
    load_pair(smb + SM_W,  Whi, Wlo, (size_t)h0, K, 0, tid);
    load_pair(smb + SM_X0, Xhi, Xlo, (size_t)batch * T_ + toff, K, 0, tid);
    CP_COMMIT();

    for (int tg = 0; tg < NTG; tg++) {
        #pragma unroll 1
        for (int s = 0; s < STEPS; s++) {
            const int kc = s >> 1, tt = s & 1;
            CP_WAIT0();                           // this step's tiles in smem
            __syncthreads();
            FENCE_ASYNC();
            if (wid == 0 && elect_one_pred()) {
                issue12(smb, smb + SM_X0 + (uint32_t)tt * XBUF_SZ, tmem + tt * 128, kc == 0);
                TC_COMMIT(tt ? (smb + SM_MB1) : (smb + SM_MB0));
            }
            if (tt) c1++; else c0++;

            if (s + 1 < STEPS) {
                const int nkc = (s + 1) >> 1, ntt = (s + 1) & 1;
                // X buf ntt: last reader = MMA step s-1 (commit #cnt[ntt]); alias-free (issued==target)
                if (ntt == 0) {
                    if (c0 >= 1) MBAR_WAIT(smb + SM_MB0, (c0 - 1) & 1);
                    // W overwrite also needs MMA s (just committed to mbar1, #c1)
                    MBAR_WAIT(smb + SM_MB1, (c1 - 1) & 1);
                    load_pair(smb + SM_W, Whi, Wlo, (size_t)h0, K, nkc * KC, tid);
                } else {
                    if (c1 >= 1) MBAR_WAIT(smb + SM_MB1, (c1 - 1) & 1);
                }
                load_pair(smb + SM_X0 + (uint32_t)ntt * XBUF_SZ, Xhi, Xlo,
                          (size_t)batch * T_ + toff + (tg * 2 + ntt) * 128, K, nkc * KC, tid);
                CP_COMMIT();
            } else {
                // end of tilegroup: drain both mbars (alias-free: issued==target)
                MBAR_WAIT(smb + SM_MB0, (c0 - 1) & 1);
                MBAR_WAIT(smb + SM_MB1, (c1 - 1) & 1);
                if (tg + 1 < NTG) {   // preload next tg (overlaps epilogue)
                    load_pair(smb + SM_W,  Whi, Wlo, (size_t)h0, K, 0, tid);
                    load_pair(smb + SM_X0, Xhi, Xlo,
                              (size_t)batch * T_ + toff + (tg + 1) * 256, K, 0, tid);
                    CP_COMMIT();
                }
            }
        }
        // ---------------- epilogue ----------------
        if (tid < 128) {
            TC_FENCE_AFTER();
            #pragma unroll
            for (int tt = 0; tt < 2; tt++) {
                #pragma unroll
                for (int cb = 0; cb < 4; cb++) {
                    uint32_t d[32];
                    LDTM_X32(d, tmem + tt * 128 + cb * 32);
                    TC_WAIT_LD();
                    const int tglob = toff + (tg * 2 + tt) * 128 + cb * 32;
                    if (EPI_SCAN) {
                        const size_t base = ((size_t)batch * T_ + tglob) * H_ + h0 + tid;
                        #pragma unroll
                        for (int i = 0; i < 32; i++) {
                            float p = __uint_as_float(d[i]) + bi;
                            carry = fmaxf(fmaf(uu, carry, p), 0.0f);
                            __nv_bfloat16 hb = __float2bfloat16(carry);
                            Hhi[base + (size_t)i * H_] = hb;
                            Hlo[base + (size_t)i * H_] =
                                __float2bfloat16(carry - __bfloat162float(hb));
                        }
                    } else {
                        float* op = fout + ((size_t)batch * T_ + tglob) * DOUT + tid;
                        #pragma unroll
                        for (int i = 0; i < 32; i++)
                            op[(size_t)i * DOUT] = __uint_as_float(d[i]) + bi;
                    }
                }
            }
            TC_FENCE_BEFORE();
        }
        __syncthreads();   // epilogue done before next tg's en=0 MMA overwrites TMEM
    }
    if (tid == 0) { MBAR_INVAL(smb + SM_MB0); MBAR_INVAL(smb + SM_MB1); }
    __syncthreads();
    if (wid == 0) TC_DEALLOC(tmem, 256);
#else
    // SIMT fallback: thread tid<128 owns channel h0+tid; covers its t-range serially.
    float* xrow = (float*)smem;
    const int hh = h0 + (tid < 128 ? tid : 0);
    const int tcount = EPI_SCAN ? T_ : T_ / 2;
    float uu = 0.0f, bi = 0.0f;
    if (tid < 128) {
        bi = bl[hh] + (EPI_SCAN ? bb[hh] : 0.0f);
        if (EPI_SCAN) uu = u[hh];
    }
    const __nv_bfloat16* wh = Whi + (size_t)hh * K;
    const __nv_bfloat16* wl = Wlo + (size_t)hh * K;
    float hcar = 0.0f;
    for (int tt = 0; tt < tcount; tt++) {
        const int t = toff + tt;
        __syncthreads();
        size_t xr = ((size_t)batch * T_ + t) * K;
        for (int i = tid; i < K; i += blockDim.x)
            xrow[i] = __bfloat162float(Xhi[xr + i]) + __bfloat162float(Xlo[xr + i]);
        __syncthreads();
        if (tid < 128) {
            float acc = 0.0f;
            for (int k = 0; k < K; k++)
                acc += (__bfloat162float(wh[k]) + __bfloat162float(wl[k])) * xrow[k];
            if (EPI_SCAN) {
                hcar = fmaxf(acc + bi + uu * hcar, 0.0f);
                size_t oi = ((size_t)batch * T_ + t) * H_ + hh;
                __nv_bfloat16 hb = __float2bfloat16(hcar);
                Hhi[oi] = hb;
                Hlo[oi] = __float2bfloat16(hcar - __bfloat162float(hb));
            } else {
                fout[((size_t)batch * T_ + t) * DOUT + tid] = acc + bi;
            }
        }
    }
#endif
}

extern "C" void kernel_launch(void* const* d_in, const int* in_sizes, int n_in,
                              void* d_out, int out_size) {
    const float* x   = (const float*)d_in[0];
    const float* W0  = (const float*)d_in[1];
    const float* bl0 = (const float*)d_in[2];
    const float* u0  = (const float*)d_in[3];
    const float* bb0 = (const float*)d_in[4];
    const float* W1  = (const float*)d_in[5];
    const float* bl1 = (const float*)d_in[6];
    const float* u1  = (const float*)d_in[7];
    const float* bb1 = (const float*)d_in[8];
    const float* fcW = (const float*)d_in[9];
    const float* fcb = (const float*)d_in[10];
    float* out = (float*)d_out;

    __nv_bfloat16 *xhi, *xlo, *h1hi, *h1lo, *h2hi, *h2lo;
    __nv_bfloat16 *w0hi, *w0lo, *w1hi, *w1lo, *fwhi, *fwlo;
    cudaGetSymbolAddress((void**)&xhi,  g_xhi);
    cudaGetSymbolAddress((void**)&xlo,  g_xlo);
    cudaGetSymbolAddress((void**)&h1hi, g_h1hi);
    cudaGetSymbolAddress((void**)&h1lo, g_h1lo);
    cudaGetSymbolAddress((void**)&h2hi, g_h2hi);
    cudaGetSymbolAddress((void**)&h2lo, g_h2lo);
    cudaGetSymbolAddress((void**)&w0hi, g_W0hi);
    cudaGetSymbolAddress((void**)&w0lo, g_W0lo);
    cudaGetSymbolAddress((void**)&w1hi, g_W1hi);
    cudaGetSymbolAddress((void**)&w1lo, g_W1lo);
    cudaGetSymbolAddress((void**)&fwhi, g_fWhi);
    cudaGetSymbolAddress((void**)&fwlo, g_fWlo);

    cudaFuncSetAttribute(gemm_tc<DIN, 1>, cudaFuncAttributeMaxDynamicSharedMemorySize, SM_TOTAL);
    cudaFuncSetAttribute(gemm_tc<H_, 1>,  cudaFuncAttributeMaxDynamicSharedMemorySize, SM_TOTAL);
    cudaFuncSetAttribute(gemm_tc<H_, 0>,  cudaFuncAttributeMaxDynamicSharedMemorySize, SM_TOTAL);

    split_all<<<2048, 256>>>(x, W0, W1, fcW, xhi, xlo, w0hi, w0lo, w1hi, w1lo, fwhi, fwlo);

    dim3 lgrid(H_ / 128, B_);     // (4, 64)
    gemm_tc<DIN, 1><<<lgrid, TPB, SM_TOTAL>>>(xhi, xlo, w0hi, w0lo, bl0, u0, bb0,
                                              h1hi, h1lo, nullptr);
    gemm_tc<H_, 1> <<<lgrid, TPB, SM_TOTAL>>>(h1hi, h1lo, w1hi, w1lo, bl1, u1, bb1,
                                              h2hi, h2lo, nullptr);
    dim3 fgrid(2, B_);            // (2, 64)
    gemm_tc<H_, 0> <<<fgrid, TPB, SM_TOTAL>>>(h2hi, h2lo, fwhi, fwlo, fcb, nullptr, nullptr,
                                              nullptr, nullptr, out);
}